// round 7
// baseline (speedup 1.0000x reference)
#include <cuda_runtime.h>

#define B_TOT   8192
#define T_IN    1024
#define T_OUT   1088               // 1024 + 64 free-running
#define EPB     64                 // elements per block; e0=lane, e1=lane+32
#define THREADS 192                // 6 warps, each owns 2 hidden units
#define CHUNK   32
#define NCHUNK  (T_OUT / CHUNK)    // 34
#define XST     65                 // xbuf row stride (ull), conflict-free
#define YST     65                 // ybuf row stride (float)
#define HST     14                 // h-exchange row stride (ull), conflict-free LDS.128

typedef unsigned long long ull;

__device__ __forceinline__ ull pk2(float lo, float hi) {
    ull r; asm("mov.b64 %0, {%1, %2};" : "=l"(r) : "f"(lo), "f"(hi)); return r;
}
__device__ __forceinline__ ull ffma2(ull a, ull b, ull c) {
    ull d; asm("fma.rn.f32x2 %0, %1, %2, %3;" : "=l"(d) : "l"(a), "l"(b), "l"(c)); return d;
}
__device__ __forceinline__ float2 unpk(ull v) {
    float lo, hi; asm("mov.b64 {%0, %1}, %2;" : "=f"(lo), "=f"(hi) : "l"(v));
    return make_float2(lo, hi);
}
__device__ __forceinline__ float tanh_fast(float x) {
    float y; asm("tanh.approx.f32 %0, %1;" : "=f"(y) : "f"(x)); return y;
}
__device__ __forceinline__ float sigf(float x) {
    return fmaf(tanh_fast(0.5f * x), 0.5f, 0.5f);
}

// one pair-row dot for BOTH elements: 6 broadcast LDS.128 feed 24 FFMA2
__device__ __forceinline__ void dot2(const ull* __restrict__ row,
                                     const ull* ha, const ull* hb,
                                     ull& a0, ull& a1) {
    const ulonglong2* p = (const ulonglong2*)row;
    #pragma unroll
    for (int jj = 0; jj < 6; jj++) {
        ulonglong2 v = p[jj];
        a0 = ffma2(ha[2 * jj],     v.x, a0);
        a0 = ffma2(ha[2 * jj + 1], v.y, a0);
        a1 = ffma2(hb[2 * jj],     v.x, a1);
        a1 = ffma2(hb[2 * jj + 1], v.y, a1);
    }
}

__global__ __launch_bounds__(THREADS)
void lstm_seq_kernel(const float* __restrict__ input,
                     const float* __restrict__ w_ih1, const float* __restrict__ w_hh1,
                     const float* __restrict__ b_ih1, const float* __restrict__ b_hh1,
                     const float* __restrict__ w_ih2, const float* __restrict__ w_hh2,
                     const float* __restrict__ b_ih2, const float* __restrict__ b_hh2,
                     const float* __restrict__ w_lin, const float* __restrict__ b_lin,
                     float* __restrict__ out)
{
    // gate-packed weights: per unit u, pair 0=(i,f), 1=(g,o);
    // s[u*24 + pair*12 + j] = pk2(W[gA*12+u][j], W[gB*12+u][j])
    __shared__ alignas(16) ull s_pk1[288], s_pki2[288], s_pkh2[288];
    __shared__ alignas(16) ull s_wl[12];            // pk2(wl_j, wl_j)
    __shared__ alignas(16) ull xbuf[CHUNK * XST];   // pre-packed (x,x)
    __shared__ alignas(16) float ybuf[CHUNK * YST];
    __shared__ alignas(16) ull h1buf[EPB * HST];    // pre-packed (h,h) per [e][j]
    __shared__ alignas(16) ull h2buf[EPB * HST];

    const int tid  = threadIdx.x;
    const int wid  = tid >> 5;        // warp 0..5, owns units 2w, 2w+1
    const int lane = tid & 31;
    const int u0   = wid * 2;

    // ---- stage packed weights ----
    for (int idx = tid; idx < 288; idx += THREADS) {
        int u = idx / 24, rem = idx % 24, pair = rem / 12, j = rem % 12;
        int rA = (pair ? 24 : 0) + u;
        int rB = (pair ? 36 : 12) + u;
        s_pk1[idx]  = pk2(w_hh1[rA * 12 + j], w_hh1[rB * 12 + j]);
        s_pki2[idx] = pk2(w_ih2[rA * 12 + j], w_ih2[rB * 12 + j]);
        s_pkh2[idx] = pk2(w_hh2[rA * 12 + j], w_hh2[rB * 12 + j]);
    }
    if (tid < 12) s_wl[tid] = pk2(w_lin[tid], w_lin[tid]);

    // per-warp packed constants
    ull wx_if[2], wx_go[2], bz1_if[2], bz1_go[2], bz2_if[2], bz2_go[2];
    #pragma unroll
    for (int m = 0; m < 2; m++) {
        const int u = u0 + m;
        wx_if[m]  = pk2(w_ih1[u],      w_ih1[12 + u]);
        wx_go[m]  = pk2(w_ih1[24 + u], w_ih1[36 + u]);
        bz1_if[m] = pk2(b_ih1[u] + b_hh1[u],           b_ih1[12 + u] + b_hh1[12 + u]);
        bz1_go[m] = pk2(b_ih1[24 + u] + b_hh1[24 + u], b_ih1[36 + u] + b_hh1[36 + u]);
        bz2_if[m] = pk2(b_ih2[u] + b_hh2[u],           b_ih2[12 + u] + b_hh2[12 + u]);
        bz2_go[m] = pk2(b_ih2[24 + u] + b_hh2[24 + u], b_ih2[36 + u] + b_hh2[36 + u]);
    }
    const float blin = b_lin[0];

    // state: packed-replicated h per element, c private to owned units
    ull hh1a[12], hh1b[12], hh2a[12], hh2b[12];
    float c1a[2], c1b[2], c2a[2], c2b[2];
    #pragma unroll
    for (int j = 0; j < 12; j++) { hh1a[j] = 0ULL; hh1b[j] = 0ULL; hh2a[j] = 0ULL; hh2b[j] = 0ULL; }
    #pragma unroll
    for (int m = 0; m < 2; m++) { c1a[m] = c1b[m] = c2a[m] = c2b[m] = 0.0f; }

    const size_t eg0 = (size_t)blockIdx.x * EPB;

    __syncthreads();   // weights staged

    for (int ck = 0; ck < NCHUNK; ck++) {
        const int tbase = ck * CHUNK;

        // ---- stage x chunk, pre-packed (x,x): threads 0..127, 2 per element ----
        if (tid < 128) {
            const int e    = tid & 63;
            const int half = tid >> 6;          // covers 16 of the 32 steps
            const float* src = input + (eg0 + e) * T_IN;
            if (tbase < T_IN) {
                const float4* p = (const float4*)(src + tbase + half * 16);
                #pragma unroll
                for (int q = 0; q < 4; q++) {
                    float4 v = p[q];
                    const int t0 = half * 16 + q * 4;
                    xbuf[(t0 + 0) * XST + e] = pk2(v.x, v.x);
                    xbuf[(t0 + 1) * XST + e] = pk2(v.y, v.y);
                    xbuf[(t0 + 2) * XST + e] = pk2(v.z, v.z);
                    xbuf[(t0 + 3) * XST + e] = pk2(v.w, v.w);
                }
            } else {
                const ull xv = pk2(src[T_IN - 1], src[T_IN - 1]);  // free-running
                #pragma unroll
                for (int k = 0; k < 16; k++)
                    xbuf[(half * 16 + k) * XST + e] = xv;
            }
        }
        __syncthreads();

        #pragma unroll 1
        for (int i = 0; i < CHUNK; i++) {
            const ull xx0 = xbuf[i * XST + lane];
            const ull xx1 = xbuf[i * XST + lane + 32];

            // ---------- layer 1 (2 units, 2 elements) ----------
            #pragma unroll
            for (int m = 0; m < 2; m++) {
                const int u = u0 + m;
                ull aif0 = ffma2(xx0, wx_if[m], bz1_if[m]);
                ull ago0 = ffma2(xx0, wx_go[m], bz1_go[m]);
                ull aif1 = ffma2(xx1, wx_if[m], bz1_if[m]);
                ull ago1 = ffma2(xx1, wx_go[m], bz1_go[m]);
                dot2(&s_pk1[u * 24],      hh1a, hh1b, aif0, aif1);
                dot2(&s_pk1[u * 24 + 12], hh1a, hh1b, ago0, ago1);
                {
                    float2 gif = unpk(aif0), ggo = unpk(ago0);
                    float cc = fmaf(sigf(gif.y), c1a[m], sigf(gif.x) * tanh_fast(ggo.x));
                    c1a[m] = cc;
                    float hn = sigf(ggo.y) * tanh_fast(cc);
                    h1buf[lane * HST + u] = pk2(hn, hn);
                }
                {
                    float2 gif = unpk(aif1), ggo = unpk(ago1);
                    float cc = fmaf(sigf(gif.y), c1b[m], sigf(gif.x) * tanh_fast(ggo.x));
                    c1b[m] = cc;
                    float hn = sigf(ggo.y) * tanh_fast(cc);
                    h1buf[(lane + 32) * HST + u] = pk2(hn, hn);
                }
            }
            __syncthreads();
            #pragma unroll
            for (int jj = 0; jj < 6; jj++) {
                ulonglong2 v = *(const ulonglong2*)&h1buf[lane * HST + 2 * jj];
                hh1a[2 * jj] = v.x; hh1a[2 * jj + 1] = v.y;
                ulonglong2 w = *(const ulonglong2*)&h1buf[(lane + 32) * HST + 2 * jj];
                hh1b[2 * jj] = w.x; hh1b[2 * jj + 1] = w.y;
            }

            // ---------- layer 2 ----------
            #pragma unroll
            for (int m = 0; m < 2; m++) {
                const int u = u0 + m;
                ull aif0 = bz2_if[m], ago0 = bz2_go[m];
                ull aif1 = bz2_if[m], ago1 = bz2_go[m];
                dot2(&s_pki2[u * 24],      hh1a, hh1b, aif0, aif1);
                dot2(&s_pki2[u * 24 + 12], hh1a, hh1b, ago0, ago1);
                dot2(&s_pkh2[u * 24],      hh2a, hh2b, aif0, aif1);
                dot2(&s_pkh2[u * 24 + 12], hh2a, hh2b, ago0, ago1);
                {
                    float2 gif = unpk(aif0), ggo = unpk(ago0);
                    float cc = fmaf(sigf(gif.y), c2a[m], sigf(gif.x) * tanh_fast(ggo.x));
                    c2a[m] = cc;
                    float hn = sigf(ggo.y) * tanh_fast(cc);
                    h2buf[lane * HST + u] = pk2(hn, hn);
                }
                {
                    float2 gif = unpk(aif1), ggo = unpk(ago1);
                    float cc = fmaf(sigf(gif.y), c2b[m], sigf(gif.x) * tanh_fast(ggo.x));
                    c2b[m] = cc;
                    float hn = sigf(ggo.y) * tanh_fast(cc);
                    h2buf[(lane + 32) * HST + u] = pk2(hn, hn);
                }
            }
            __syncthreads();
            #pragma unroll
            for (int jj = 0; jj < 6; jj++) {
                ulonglong2 v = *(const ulonglong2*)&h2buf[lane * HST + 2 * jj];
                hh2a[2 * jj] = v.x; hh2a[2 * jj + 1] = v.y;
                ulonglong2 w = *(const ulonglong2*)&h2buf[(lane + 32) * HST + 2 * jj];
                hh2b[2 * jj] = w.x; hh2b[2 * jj + 1] = w.y;
            }

            // ---------- linear head (warp 0 only; has full h2 for both elems) ----
            if (wid == 0) {
                ull y0 = pk2(blin, blin), y1 = y0;
                #pragma unroll
                for (int j = 0; j < 12; j++) {
                    ull wl = s_wl[j];
                    y0 = ffma2(hh2a[j], wl, y0);
                    y1 = ffma2(hh2b[j], wl, y1);
                }
                ybuf[i * YST + lane]      = unpk(y0).x;
                ybuf[i * YST + lane + 32] = unpk(y1).x;
            }
        }
        __syncthreads();   // ybuf complete

        // ---- drain y chunk to gmem (coalesced float4) ----
        for (int idx = tid; idx < EPB * 8; idx += THREADS) {
            const int e = idx >> 3, q = idx & 7;
            float4 v;
            v.x = ybuf[(q * 4 + 0) * YST + e];
            v.y = ybuf[(q * 4 + 1) * YST + e];
            v.z = ybuf[(q * 4 + 2) * YST + e];
            v.w = ybuf[(q * 4 + 3) * YST + e];
            *(float4*)(out + (eg0 + e) * T_OUT + tbase + q * 4) = v;
        }
    }
}

extern "C" void kernel_launch(void* const* d_in, const int* in_sizes, int n_in,
                              void* d_out, int out_size) {
    // metadata order: input, future(int scalar), w_ih1, w_hh1, b_ih1, b_hh1,
    //                 w_ih2, w_hh2, b_ih2, b_hh2, w_lin, b_lin
    int base = (n_in >= 12 && in_sizes[1] == 1) ? 2 : 1;  // skip 'future' scalar if present
    const float* input = (const float*)d_in[0];
    const float* w_ih1 = (const float*)d_in[base + 0];
    const float* w_hh1 = (const float*)d_in[base + 1];
    const float* b_ih1 = (const float*)d_in[base + 2];
    const float* b_hh1 = (const float*)d_in[base + 3];
    const float* w_ih2 = (const float*)d_in[base + 4];
    const float* w_hh2 = (const float*)d_in[base + 5];
    const float* b_ih2 = (const float*)d_in[base + 6];
    const float* b_hh2 = (const float*)d_in[base + 7];
    const float* w_lin = (const float*)d_in[base + 8];
    const float* b_lin = (const float*)d_in[base + 9];

    lstm_seq_kernel<<<B_TOT / EPB, THREADS>>>(
        input, w_ih1, w_hh1, b_ih1, b_hh1,
        w_ih2, w_hh2, b_ih2, b_hh2, w_lin, b_lin,
        (float*)d_out);
}

// round 8
// speedup vs baseline: 1.2197x; 1.2197x over previous
#include <cuda_runtime.h>

#define B_TOT   8192
#define T_IN    1024
#define T_OUT   1088               // 1024 + 64 free-running
#define EPB     32                 // elements per block; lane handles e and e+16
#define THREADS 96                 // 3 warps; warp w: lanes0-15 -> units 4w..4w+1,
                                   //           lanes16-31 -> units 4w+2..4w+3
#define CHUNK   32
#define NCHUNK  (T_OUT / CHUNK)    // 34
#define XST     33                 // xbuf row stride (ull)
#define YST     33                 // ybuf row stride (float)
#define HST     14                 // h-exchange row stride (ull): 7 float4 (odd) -> conflict-free

typedef unsigned long long ull;

__device__ __forceinline__ ull pk2(float lo, float hi) {
    ull r; asm("mov.b64 %0, {%1, %2};" : "=l"(r) : "f"(lo), "f"(hi)); return r;
}
__device__ __forceinline__ ull ffma2(ull a, ull b, ull c) {
    ull d; asm("fma.rn.f32x2 %0, %1, %2, %3;" : "=l"(d) : "l"(a), "l"(b), "l"(c)); return d;
}
__device__ __forceinline__ float2 unpk(ull v) {
    float lo, hi; asm("mov.b64 {%0, %1}, %2;" : "=f"(lo), "=f"(hi) : "l"(v));
    return make_float2(lo, hi);
}
__device__ __forceinline__ float tanh_fast(float x) {
    float y; asm("tanh.approx.f32 %0, %1;" : "=f"(y) : "f"(x)); return y;
}
__device__ __forceinline__ float sigf(float x) {
    return fmaf(tanh_fast(0.5f * x), 0.5f, 0.5f);
}

// pair-row dot for BOTH elements. p points at this lane's group slot; successive
// jj entries are 6 ulonglong2 apart (group-minor layout). 6 LDS.128 -> 24 FFMA2.
__device__ __forceinline__ void dot2s(const ulonglong2* __restrict__ p,
                                      const ull* ha, const ull* hb,
                                      ull& a0, ull& a1) {
    #pragma unroll
    for (int jj = 0; jj < 6; jj++) {
        ulonglong2 v = p[jj * 6];
        a0 = ffma2(ha[2 * jj],     v.x, a0);
        a0 = ffma2(ha[2 * jj + 1], v.y, a0);
        a1 = ffma2(hb[2 * jj],     v.x, a1);
        a1 = ffma2(hb[2 * jj + 1], v.y, a1);
    }
}

__global__ __launch_bounds__(THREADS)
void lstm_seq_kernel(const float* __restrict__ input,
                     const float* __restrict__ w_ih1, const float* __restrict__ w_hh1,
                     const float* __restrict__ b_ih1, const float* __restrict__ b_hh1,
                     const float* __restrict__ w_ih2, const float* __restrict__ w_hh2,
                     const float* __restrict__ b_ih2, const float* __restrict__ b_hh2,
                     const float* __restrict__ w_lin, const float* __restrict__ b_lin,
                     float* __restrict__ out)
{
    // group-minor gate-packed weights:
    // flat ull index = (pos*6 + g)*2 + t, pos = (m*2+pair)*6 + jj, j = 2*jj+t,
    // value = pk2(W[rA*12+j], W[rB*12+j]); pair0=(i,f): rA=u, rB=12+u;
    // pair1=(g,o): rA=24+u, rB=36+u; u = 2g+m.
    __shared__ alignas(16) ull s_pk1[288], s_pki2[288], s_pkh2[288];
    __shared__ alignas(16) ull s_wl[12];            // pk2(wl_j, wl_j)
    __shared__ alignas(16) ull xbuf[CHUNK * XST];   // pre-packed (x,x)
    __shared__ alignas(16) float ybuf[CHUNK * YST];
    __shared__ alignas(16) ull h1buf[EPB * HST];    // pre-packed (h,h) per [e][j]
    __shared__ alignas(16) ull h2buf[EPB * HST];

    const int tid  = threadIdx.x;
    const int wid  = tid >> 5;
    const int lane = tid & 31;
    const int g    = 2 * wid + (lane >> 4);   // unit-group 0..5 (units 2g, 2g+1)
    const int e0   = lane & 15;
    const int e1   = e0 + 16;

    // ---- stage packed weights (group-minor) ----
    for (int idx = tid; idx < 288; idx += THREADS) {
        int pos = idx / 12, rem = idx % 12, gg = rem >> 1, t = rem & 1;
        int m = pos / 12, rem2 = pos % 12, pair = rem2 / 6, jj = rem2 % 6;
        int j = jj * 2 + t;
        int u = 2 * gg + m;
        int rA = (pair ? 24 : 0) + u;
        int rB = (pair ? 36 : 12) + u;
        s_pk1[idx]  = pk2(w_hh1[rA * 12 + j], w_hh1[rB * 12 + j]);
        s_pki2[idx] = pk2(w_ih2[rA * 12 + j], w_ih2[rB * 12 + j]);
        s_pkh2[idx] = pk2(w_hh2[rA * 12 + j], w_hh2[rB * 12 + j]);
    }
    if (tid < 12) s_wl[tid] = pk2(w_lin[tid], w_lin[tid]);

    // per-lane packed constants (2 owned units)
    ull wx_if[2], wx_go[2], bz1_if[2], bz1_go[2], bz2_if[2], bz2_go[2];
    #pragma unroll
    for (int m = 0; m < 2; m++) {
        const int u = 2 * g + m;
        wx_if[m]  = pk2(w_ih1[u],      w_ih1[12 + u]);
        wx_go[m]  = pk2(w_ih1[24 + u], w_ih1[36 + u]);
        bz1_if[m] = pk2(b_ih1[u] + b_hh1[u],           b_ih1[12 + u] + b_hh1[12 + u]);
        bz1_go[m] = pk2(b_ih1[24 + u] + b_hh1[24 + u], b_ih1[36 + u] + b_hh1[36 + u]);
        bz2_if[m] = pk2(b_ih2[u] + b_hh2[u],           b_ih2[12 + u] + b_hh2[12 + u]);
        bz2_go[m] = pk2(b_ih2[24 + u] + b_hh2[24 + u], b_ih2[36 + u] + b_hh2[36 + u]);
    }
    const float blin = b_lin[0];

    // state: packed-replicated h per element, c private to owned units
    ull hh1a[12], hh1b[12], hh2a[12], hh2b[12];
    float c1a[2], c1b[2], c2a[2], c2b[2];
    #pragma unroll
    for (int j = 0; j < 12; j++) { hh1a[j] = 0ULL; hh1b[j] = 0ULL; hh2a[j] = 0ULL; hh2b[j] = 0ULL; }
    #pragma unroll
    for (int m = 0; m < 2; m++) { c1a[m] = c1b[m] = c2a[m] = c2b[m] = 0.0f; }

    const size_t eg0 = (size_t)blockIdx.x * EPB;

    const ulonglong2* s2_pk1  = (const ulonglong2*)s_pk1;
    const ulonglong2* s2_pki2 = (const ulonglong2*)s_pki2;
    const ulonglong2* s2_pkh2 = (const ulonglong2*)s_pkh2;

    for (int ck = 0; ck < NCHUNK; ck++) {
        const int tbase = ck * CHUNK;

        // ---- stage x chunk, pre-packed (x,x): threads 0..63 (2 per element) ----
        if (tid < 64) {
            const int e    = tid & 31;
            const int half = tid >> 5;          // 16 of the 32 steps each
            const float* src = input + (eg0 + e) * T_IN;
            if (tbase < T_IN) {
                const float4* p = (const float4*)(src + tbase + half * 16);
                #pragma unroll
                for (int q = 0; q < 4; q++) {
                    float4 v = p[q];
                    const int t0 = half * 16 + q * 4;
                    xbuf[(t0 + 0) * XST + e] = pk2(v.x, v.x);
                    xbuf[(t0 + 1) * XST + e] = pk2(v.y, v.y);
                    xbuf[(t0 + 2) * XST + e] = pk2(v.z, v.z);
                    xbuf[(t0 + 3) * XST + e] = pk2(v.w, v.w);
                }
            } else {
                const ull xv = pk2(src[T_IN - 1], src[T_IN - 1]);  // free-running
                #pragma unroll
                for (int k = 0; k < 16; k++)
                    xbuf[(half * 16 + k) * XST + e] = xv;
            }
        }
        __syncthreads();

        #pragma unroll 1
        for (int i = 0; i < CHUNK; i++) {
            const ull xx0 = xbuf[i * XST + e0];
            const ull xx1 = xbuf[i * XST + e1];

            // ---------- layer 1 (2 units x 2 elements) ----------
            float hn0[2], hn1[2];
            #pragma unroll
            for (int m = 0; m < 2; m++) {
                ull aif0 = ffma2(xx0, wx_if[m], bz1_if[m]);
                ull ago0 = ffma2(xx0, wx_go[m], bz1_go[m]);
                ull aif1 = ffma2(xx1, wx_if[m], bz1_if[m]);
                ull ago1 = ffma2(xx1, wx_go[m], bz1_go[m]);
                dot2s(s2_pk1 + ((m * 2 + 0) * 6) * 6 + g, hh1a, hh1b, aif0, aif1);
                dot2s(s2_pk1 + ((m * 2 + 1) * 6) * 6 + g, hh1a, hh1b, ago0, ago1);
                {
                    float2 gif = unpk(aif0), ggo = unpk(ago0);
                    float cc = fmaf(sigf(gif.y), c1a[m], sigf(gif.x) * tanh_fast(ggo.x));
                    c1a[m] = cc;
                    hn0[m] = sigf(ggo.y) * tanh_fast(cc);
                }
                {
                    float2 gif = unpk(aif1), ggo = unpk(ago1);
                    float cc = fmaf(sigf(gif.y), c1b[m], sigf(gif.x) * tanh_fast(ggo.x));
                    c1b[m] = cc;
                    hn1[m] = sigf(ggo.y) * tanh_fast(cc);
                }
            }
            // publish (h[2g], h[2g+1]) for both elements: 2x STS.128, conflict-free
            {
                ulonglong2 v0; v0.x = pk2(hn0[0], hn0[0]); v0.y = pk2(hn0[1], hn0[1]);
                *(ulonglong2*)&h1buf[e0 * HST + 2 * g] = v0;
                ulonglong2 v1; v1.x = pk2(hn1[0], hn1[0]); v1.y = pk2(hn1[1], hn1[1]);
                *(ulonglong2*)&h1buf[e1 * HST + 2 * g] = v1;
            }
            __syncthreads();
            #pragma unroll
            for (int jj = 0; jj < 6; jj++) {
                ulonglong2 v = *(const ulonglong2*)&h1buf[e0 * HST + 2 * jj];
                hh1a[2 * jj] = v.x; hh1a[2 * jj + 1] = v.y;
                ulonglong2 w = *(const ulonglong2*)&h1buf[e1 * HST + 2 * jj];
                hh1b[2 * jj] = w.x; hh1b[2 * jj + 1] = w.y;
            }

            // ---------- layer 2 ----------
            #pragma unroll
            for (int m = 0; m < 2; m++) {
                ull aif0 = bz2_if[m], ago0 = bz2_go[m];
                ull aif1 = bz2_if[m], ago1 = bz2_go[m];
                dot2s(s2_pki2 + ((m * 2 + 0) * 6) * 6 + g, hh1a, hh1b, aif0, aif1);
                dot2s(s2_pki2 + ((m * 2 + 1) * 6) * 6 + g, hh1a, hh1b, ago0, ago1);
                dot2s(s2_pkh2 + ((m * 2 + 0) * 6) * 6 + g, hh2a, hh2b, aif0, aif1);
                dot2s(s2_pkh2 + ((m * 2 + 1) * 6) * 6 + g, hh2a, hh2b, ago0, ago1);
                {
                    float2 gif = unpk(aif0), ggo = unpk(ago0);
                    float cc = fmaf(sigf(gif.y), c2a[m], sigf(gif.x) * tanh_fast(ggo.x));
                    c2a[m] = cc;
                    hn0[m] = sigf(ggo.y) * tanh_fast(cc);
                }
                {
                    float2 gif = unpk(aif1), ggo = unpk(ago1);
                    float cc = fmaf(sigf(gif.y), c2b[m], sigf(gif.x) * tanh_fast(ggo.x));
                    c2b[m] = cc;
                    hn1[m] = sigf(ggo.y) * tanh_fast(cc);
                }
            }
            {
                ulonglong2 v0; v0.x = pk2(hn0[0], hn0[0]); v0.y = pk2(hn0[1], hn0[1]);
                *(ulonglong2*)&h2buf[e0 * HST + 2 * g] = v0;
                ulonglong2 v1; v1.x = pk2(hn1[0], hn1[0]); v1.y = pk2(hn1[1], hn1[1]);
                *(ulonglong2*)&h2buf[e1 * HST + 2 * g] = v1;
            }
            __syncthreads();
            #pragma unroll
            for (int jj = 0; jj < 6; jj++) {
                ulonglong2 v = *(const ulonglong2*)&h2buf[e0 * HST + 2 * jj];
                hh2a[2 * jj] = v.x; hh2a[2 * jj + 1] = v.y;
                ulonglong2 w = *(const ulonglong2*)&h2buf[e1 * HST + 2 * jj];
                hh2b[2 * jj] = w.x; hh2b[2 * jj + 1] = w.y;
            }

            // ---------- linear head: warp 0; lane l handles element l ----------
            // (lane<16: own e0==lane via hh2a; lane>=16: own e1==lane via hh2b)
            if (wid == 0) {
                ull y0 = pk2(blin, blin), y1 = y0;
                #pragma unroll
                for (int j = 0; j < 12; j++) {
                    ull wl = s_wl[j];
                    y0 = ffma2(hh2a[j], wl, y0);
                    y1 = ffma2(hh2b[j], wl, y1);
                }
                ybuf[i * YST + lane] = (lane < 16) ? unpk(y0).x : unpk(y1).x;
            }
        }
        __syncthreads();   // ybuf complete

        // ---- drain y chunk to gmem (float4 stores) ----
        if (tid < 64) {
            const int e = tid & 31, half = tid >> 5;
            #pragma unroll
            for (int q = 0; q < 4; q++) {
                const int t0 = half * 16 + q * 4;
                float4 v;
                v.x = ybuf[(t0 + 0) * YST + e];
                v.y = ybuf[(t0 + 1) * YST + e];
                v.z = ybuf[(t0 + 2) * YST + e];
                v.w = ybuf[(t0 + 3) * YST + e];
                *(float4*)(out + (eg0 + e) * T_OUT + tbase + t0) = v;
            }
        }
    }
}

extern "C" void kernel_launch(void* const* d_in, const int* in_sizes, int n_in,
                              void* d_out, int out_size) {
    // metadata order: input, future(int scalar), w_ih1, w_hh1, b_ih1, b_hh1,
    //                 w_ih2, w_hh2, b_ih2, b_hh2, w_lin, b_lin
    int base = (n_in >= 12 && in_sizes[1] == 1) ? 2 : 1;  // skip 'future' scalar if present
    const float* input = (const float*)d_in[0];
    const float* w_ih1 = (const float*)d_in[base + 0];
    const float* w_hh1 = (const float*)d_in[base + 1];
    const float* b_ih1 = (const float*)d_in[base + 2];
    const float* b_hh1 = (const float*)d_in[base + 3];
    const float* w_ih2 = (const float*)d_in[base + 4];
    const float* w_hh2 = (const float*)d_in[base + 5];
    const float* b_ih2 = (const float*)d_in[base + 6];
    const float* b_hh2 = (const float*)d_in[base + 7];
    const float* w_lin = (const float*)d_in[base + 8];
    const float* b_lin = (const float*)d_in[base + 9];

    lstm_seq_kernel<<<B_TOT / EPB, THREADS>>>(
        input, w_ih1, w_hh1, b_ih1, b_hh1,
        w_ih2, w_hh2, b_ih2, b_hh2, w_lin, b_lin,
        (float*)d_out);
}